// round 12
// baseline (speedup 1.0000x reference)
#include <cuda_runtime.h>
#include <math.h>
#include <cstdint>

#define Bdim 4
#define Nseq 2048
#define DIM 1024
#define NH 16
#define HD 64
#define SCALE 0.125f   // 1/sqrt(64)

// Scratch: [B*H, N, HD] for q, k, v. Values pre-rounded to tf32 (q pre-scaled).
__device__ float g_q[Bdim * NH * Nseq * HD];
__device__ float g_k[Bdim * NH * Nseq * HD];
__device__ float g_v[Bdim * NH * Nseq * HD];

__device__ __forceinline__ uint32_t f2tf32(float f) {
    uint32_t r;
    asm("cvt.rna.tf32.f32 %0, %1;" : "=r"(r) : "f"(f));
    return r;
}

// m16n8k8 tf32 mma. c += a * b.
__device__ __forceinline__ void mma8(float* c, uint32_t a0, uint32_t a1,
                                     uint32_t a2, uint32_t a3,
                                     uint32_t b0, uint32_t b1) {
    asm volatile(
        "mma.sync.aligned.m16n8k8.row.col.f32.tf32.tf32.f32 "
        "{%0,%1,%2,%3},{%4,%5,%6,%7},{%8,%9},{%0,%1,%2,%3};"
        : "+f"(c[0]), "+f"(c[1]), "+f"(c[2]), "+f"(c[3])
        : "r"(a0), "r"(a1), "r"(a2), "r"(a3), "r"(b0), "r"(b1));
}

// Permute k within each 8-group so (k, k+4) become adjacent floats:
// pos = group*8 + (k%4)*2 + ((k/4)%2)
__device__ __forceinline__ int perm8(int k) {
    return (k & ~7) + ((k & 3) << 1) + ((k >> 2) & 1);
}

// ---------------------------------------------------------------------------
// QKV GEMM: unchanged from Round 8 (513 us; attention is the bottleneck).
// ---------------------------------------------------------------------------
#define GP 36                       // smem row pitch (floats)
#define GEMM_SMEM (4 * 128 * GP * 4)   // 2 bufs x (A+B) = 73728 B

__global__ __launch_bounds__(256) void qkv_gemm_mma(const float* __restrict__ x,
                                                    const float* __restrict__ w,
                                                    const float* __restrict__ bias) {
    extern __shared__ float sm[];
    float* As = sm;                  // [2][128*GP]
    float* Bs = sm + 2 * 128 * GP;   // [2][128*GP]

    const int tid = threadIdx.x;
    const int wid = tid >> 5, lane = tid & 31;
    const int g = lane >> 2, tig = lane & 3;
    const int wm = (wid >> 1) * 32, wn = (wid & 1) * 64;
    const int n0 = blockIdx.x * 128;
    const int m0 = blockIdx.y * 128;
    const int c4 = tid & 7;          // float4 col index within 32-float chunk row

    float4 ar[4], br[4];
    float acc[2][8][4];
#pragma unroll
    for (int mi = 0; mi < 2; mi++)
#pragma unroll
        for (int ni = 0; ni < 8; ni++)
#pragma unroll
            for (int e = 0; e < 4; e++) acc[mi][ni][e] = 0.f;

#define LOADG(c) {                                                              \
    const float* Ap = x + (size_t)m0 * DIM + (c) * 32;                          \
    const float* Bp = w + (size_t)n0 * DIM + (c) * 32;                          \
    _Pragma("unroll")                                                           \
    for (int it = 0; it < 4; it++) {                                            \
        int r = (it * 256 + tid) >> 3;                                          \
        ar[it] = *(const float4*)(Ap + (size_t)r * DIM + c4 * 4);               \
        br[it] = *(const float4*)(Bp + (size_t)r * DIM + c4 * 4);               \
    } }

#define STORES(buf) {                                                           \
    float* ab = As + (buf) * 128 * GP;                                          \
    float* bb = Bs + (buf) * 128 * GP;                                          \
    _Pragma("unroll")                                                           \
    for (int it = 0; it < 4; it++) {                                            \
        int r = (it * 256 + tid) >> 3;                                          \
        float av[4] = {ar[it].x, ar[it].y, ar[it].z, ar[it].w};                 \
        float bv[4] = {br[it].x, br[it].y, br[it].z, br[it].w};                 \
        _Pragma("unroll")                                                       \
        for (int e = 0; e < 4; e++) {                                           \
            int p = perm8(c4 * 4 + e);                                          \
            ab[r * GP + p] = __uint_as_float(f2tf32(av[e]));                    \
            bb[r * GP + p] = __uint_as_float(f2tf32(bv[e]));                    \
        }                                                                       \
    } }

    LOADG(0);
    STORES(0);
    __syncthreads();

    int cur = 0;
    for (int c = 0; c < DIM / 32; c++) {
        if (c < DIM / 32 - 1) LOADG(c + 1);
        const float* ab = As + cur * 128 * GP;
        const float* bb = Bs + cur * 128 * GP;
#pragma unroll
        for (int s = 0; s < 4; s++) {
            float2 alo[2], ahi[2];
#pragma unroll
            for (int mi = 0; mi < 2; mi++) {
                int r0 = wm + mi * 16 + g;
                alo[mi] = *(const float2*)&ab[r0 * GP + s * 8 + tig * 2];
                ahi[mi] = *(const float2*)&ab[(r0 + 8) * GP + s * 8 + tig * 2];
            }
#pragma unroll
            for (int ni = 0; ni < 8; ni++) {
                float2 bf = *(const float2*)&bb[(wn + ni * 8 + g) * GP + s * 8 + tig * 2];
#pragma unroll
                for (int mi = 0; mi < 2; mi++) {
                    mma8(acc[mi][ni],
                         __float_as_uint(alo[mi].x), __float_as_uint(ahi[mi].x),
                         __float_as_uint(alo[mi].y), __float_as_uint(ahi[mi].y),
                         __float_as_uint(bf.x), __float_as_uint(bf.y));
                }
            }
        }
        if (c < DIM / 32 - 1) STORES(cur ^ 1);
        __syncthreads();
        cur ^= 1;
    }

    // Epilogue: bias + scale, round to tf32, scatter to g_q/g_k/g_v.
    const int nb = n0 + wn;                 // 64-aligned -> single (seg, head)
    const int seg = nb >> 10;
    const int h = (nb & 1023) >> 6;
    float* dst = (seg == 0) ? g_q : (seg == 1) ? g_k : g_v;
    const float sc = (seg == 0) ? SCALE : 1.0f;

#pragma unroll
    for (int mi = 0; mi < 2; mi++) {
        int r0 = m0 + wm + mi * 16 + g;     // and r0+8
        int bb0 = r0 >> 11;                  // /2048
        int nrow = r0 & 2047;
        float* d0 = dst + ((size_t)(bb0 * NH + h) * Nseq + nrow) * HD;
        float* d1 = d0 + 8 * HD;             // row r0+8 (same batch)
#pragma unroll
        for (int ni = 0; ni < 8; ni++) {
            int dcol = ni * 8 + 2 * tig;
            float b0 = bias[nb + dcol], b1 = bias[nb + dcol + 1];
            float2 v0, v1;
            v0.x = __uint_as_float(f2tf32((acc[mi][ni][0] + b0) * sc));
            v0.y = __uint_as_float(f2tf32((acc[mi][ni][1] + b1) * sc));
            v1.x = __uint_as_float(f2tf32((acc[mi][ni][2] + b0) * sc));
            v1.y = __uint_as_float(f2tf32((acc[mi][ni][3] + b1) * sc));
            *(float2*)&d0[dcol] = v0;
            *(float2*)&d1[dcol] = v1;
        }
    }
}

// ---------------------------------------------------------------------------
// Flash attention, tf32 mma. CTA = 128 queries x 64-key tiles, 8 warps.
// Round 9: Q fragments in registers (no Qs smem), smem 69.6KB -> 2 CTAs/SM,
// float4 K/V global loads.
// ---------------------------------------------------------------------------
#define AP 68                        // smem row pitch (floats)
#define KS_OFF 0
#define VS_OFF (64 * AP)
#define PS_OFF (128 * AP)
#define ATTN_SMEM ((PS_OFF + 128 * AP) * 4)   // 69632 B

__global__ __launch_bounds__(256, 2) void attn_mma(float* __restrict__ out) {
    extern __shared__ float sm[];
    float* Ks = sm + KS_OFF;   // [64][AP],  perm over d
    float* Vs = sm + VS_OFF;   // [64(d)][AP], transposed, perm over key
    float* Ps = sm + PS_OFF;   // [128][AP]

    const int bh = blockIdx.x;
    const int q0 = blockIdx.y * 128;
    const float* Qg = g_q + (size_t)bh * Nseq * HD;
    const float* Kg = g_k + (size_t)bh * Nseq * HD;
    const float* Vg = g_v + (size_t)bh * Nseq * HD;

    const int tid = threadIdx.x;
    const int wid = tid >> 5, lane = tid & 31;
    const int g = lane >> 2, tig = lane & 3;
    const int r0 = wid * 16 + g;           // warp-owned rows r0, r0+8

    // Q a-fragments in registers (values already tf32-rounded by GEMM).
    uint32_t qf[8][4];
    {
        const float* q0p = Qg + (size_t)(q0 + r0) * HD;
        const float* q1p = q0p + 8 * HD;
#pragma unroll
        for (int s = 0; s < 8; s++) {
            qf[s][0] = __float_as_uint(q0p[s * 8 + tig]);
            qf[s][1] = __float_as_uint(q1p[s * 8 + tig]);
            qf[s][2] = __float_as_uint(q0p[s * 8 + tig + 4]);
            qf[s][3] = __float_as_uint(q1p[s * 8 + tig + 4]);
        }
    }

    // K-load mapping: 4 threads per row, 16 floats each.
    const int krow = tid >> 2;
    const int kdc = (tid & 3) << 4;
    // V-load mapping: lane = row (conflict-free transposed stores).
    const int vrow = tid & 63;
    const int vdc = (tid >> 6) << 4;

    float o[8][4];
#pragma unroll
    for (int ni = 0; ni < 8; ni++)
#pragma unroll
        for (int e = 0; e < 4; e++) o[ni][e] = 0.f;
    float m0r = -INFINITY, m1r = -INFINITY, l0 = 0.f, l1 = 0.f;

    for (int t = 0; t < Nseq; t += 64) {
        // K tile: Ks[r][perm8(d)]
#pragma unroll
        for (int j = 0; j < 4; j++) {
            float4 k4 = *(const float4*)(Kg + (size_t)(t + krow) * HD + kdc + j * 4);
            float kv[4] = {k4.x, k4.y, k4.z, k4.w};
#pragma unroll
            for (int e = 0; e < 4; e++)
                Ks[krow * AP + perm8(kdc + j * 4 + e)] = kv[e];
        }
        // V tile transposed: Vs[d][perm8(r)]
#pragma unroll
        for (int j = 0; j < 4; j++) {
            float4 v4 = *(const float4*)(Vg + (size_t)(t + vrow) * HD + vdc + j * 4);
            float vv[4] = {v4.x, v4.y, v4.z, v4.w};
#pragma unroll
            for (int e = 0; e < 4; e++)
                Vs[(vdc + j * 4 + e) * AP + perm8(vrow)] = vv[e];
        }
        __syncthreads();

        // S = Q K^T (Q from registers)
        float sfr[8][4];
#pragma unroll
        for (int ni = 0; ni < 8; ni++)
#pragma unroll
            for (int e = 0; e < 4; e++) sfr[ni][e] = 0.f;
#pragma unroll
        for (int s = 0; s < 8; s++) {
#pragma unroll
            for (int ni = 0; ni < 8; ni++) {
                float2 kb = *(const float2*)&Ks[(ni * 8 + g) * AP + s * 8 + tig * 2];
                mma8(sfr[ni], qf[s][0], qf[s][1], qf[s][2], qf[s][3],
                     __float_as_uint(kb.x), __float_as_uint(kb.y));
            }
        }

        // Online softmax (rows r0 and r0+8; reduce across the 4 tig lanes).
        float mx0 = -INFINITY, mx1 = -INFINITY;
#pragma unroll
        for (int ni = 0; ni < 8; ni++) {
            mx0 = fmaxf(mx0, fmaxf(sfr[ni][0], sfr[ni][1]));
            mx1 = fmaxf(mx1, fmaxf(sfr[ni][2], sfr[ni][3]));
        }
        mx0 = fmaxf(mx0, __shfl_xor_sync(0xffffffffu, mx0, 1));
        mx0 = fmaxf(mx0, __shfl_xor_sync(0xffffffffu, mx0, 2));
        mx1 = fmaxf(mx1, __shfl_xor_sync(0xffffffffu, mx1, 1));
        mx1 = fmaxf(mx1, __shfl_xor_sync(0xffffffffu, mx1, 2));
        float nm0 = fmaxf(m0r, mx0), nm1 = fmaxf(m1r, mx1);
        float al0 = __expf(m0r - nm0), al1 = __expf(m1r - nm1);
        m0r = nm0; m1r = nm1;
        float rs0 = 0.f, rs1 = 0.f;
#pragma unroll
        for (int ni = 0; ni < 8; ni++) {
            sfr[ni][0] = __expf(sfr[ni][0] - nm0);
            sfr[ni][1] = __expf(sfr[ni][1] - nm0);
            sfr[ni][2] = __expf(sfr[ni][2] - nm1);
            sfr[ni][3] = __expf(sfr[ni][3] - nm1);
            rs0 += sfr[ni][0] + sfr[ni][1];
            rs1 += sfr[ni][2] + sfr[ni][3];
        }
        rs0 += __shfl_xor_sync(0xffffffffu, rs0, 1);
        rs0 += __shfl_xor_sync(0xffffffffu, rs0, 2);
        rs1 += __shfl_xor_sync(0xffffffffu, rs1, 1);
        rs1 += __shfl_xor_sync(0xffffffffu, rs1, 2);
        l0 = l0 * al0 + rs0;
        l1 = l1 * al1 + rs1;
#pragma unroll
        for (int ni = 0; ni < 8; ni++) {
            o[ni][0] *= al0; o[ni][1] *= al0;
            o[ni][2] *= al1; o[ni][3] *= al1;
        }

        // Store P (tf32-rounded) — warp-local region.
#pragma unroll
        for (int ni = 0; ni < 8; ni++) {
            float2 p0, p1;
            p0.x = __uint_as_float(f2tf32(sfr[ni][0]));
            p0.y = __uint_as_float(f2tf32(sfr[ni][1]));
            p1.x = __uint_as_float(f2tf32(sfr[ni][2]));
            p1.y = __uint_as_float(f2tf32(sfr[ni][3]));
            *(float2*)&Ps[r0 * AP + ni * 8 + 2 * tig] = p0;
            *(float2*)&Ps[(r0 + 8) * AP + ni * 8 + 2 * tig] = p1;
        }
        __syncwarp();

        // O += P V
        const uint32_t* Pu = (const uint32_t*)Ps;
#pragma unroll
        for (int s = 0; s < 8; s++) {
            uint32_t a0 = Pu[r0 * AP + s * 8 + tig];
            uint32_t a1 = Pu[(r0 + 8) * AP + s * 8 + tig];
            uint32_t a2 = Pu[r0 * AP + s * 8 + tig + 4];
            uint32_t a3 = Pu[(r0 + 8) * AP + s * 8 + tig + 4];
#pragma unroll
            for (int ni = 0; ni < 8; ni++) {
                float2 vb = *(const float2*)&Vs[(ni * 8 + g) * AP + s * 8 + tig * 2];
                mma8(o[ni], a0, a1, a2, a3,
                     __float_as_uint(vb.x), __float_as_uint(vb.y));
            }
        }
        __syncthreads();
    }

    // Final write: out[b, q, h*64 + d]
    const int bb = bh >> 4;
    const int h = bh & 15;
    float inv0 = 1.0f / l0, inv1 = 1.0f / l1;
    float* p0 = out + ((size_t)(bb * Nseq + q0 + r0)) * DIM + h * HD;
    float* p1 = out + ((size_t)(bb * Nseq + q0 + r0 + 8)) * DIM + h * HD;
#pragma unroll
    for (int ni = 0; ni < 8; ni++) {
        int d = ni * 8 + 2 * tig;
        float2 v0 = make_float2(o[ni][0] * inv0, o[ni][1] * inv0);
        float2 v1 = make_float2(o[ni][2] * inv1, o[ni][3] * inv1);
        *(float2*)&p0[d] = v0;
        *(float2*)&p1[d] = v1;
    }
}

extern "C" void kernel_launch(void* const* d_in, const int* in_sizes, int n_in,
                              void* d_out, int out_size) {
    const float* x = (const float*)d_in[0];
    const float* w = (const float*)d_in[1];
    const float* bias = (const float*)d_in[2];
    float* out = (float*)d_out;

    cudaFuncSetAttribute(qkv_gemm_mma,
                         cudaFuncAttributeMaxDynamicSharedMemorySize, GEMM_SMEM);
    cudaFuncSetAttribute(attn_mma,
                         cudaFuncAttributeMaxDynamicSharedMemorySize, ATTN_SMEM);
    cudaFuncSetAttribute(attn_mma,
                         cudaFuncAttributePreferredSharedMemoryCarveout, 100);

    dim3 ggrid(3 * DIM / 128, Bdim * Nseq / 128);  // (24, 64)
    qkv_gemm_mma<<<ggrid, 256, GEMM_SMEM>>>(x, w, bias);

    dim3 agrid(Bdim * NH, Nseq / 128);             // (64, 16)
    attn_mma<<<agrid, 256, ATTN_SMEM>>>(out);
}

// round 13
// speedup vs baseline: 1.1935x; 1.1935x over previous
#include <cuda_runtime.h>
#include <math.h>
#include <cstdint>

#define Bdim 4
#define Nseq 2048
#define DIM 1024
#define NH 16
#define HD 64
#define SCALE 0.125f   // 1/sqrt(64)

// Scratch: [B*H, N, HD] for q, k, v. Values pre-rounded to tf32 (q pre-scaled).
__device__ float g_q[Bdim * NH * Nseq * HD];
__device__ float g_k[Bdim * NH * Nseq * HD];
__device__ float g_v[Bdim * NH * Nseq * HD];

__device__ __forceinline__ uint32_t f2tf32(float f) {
    uint32_t r;
    asm("cvt.rna.tf32.f32 %0, %1;" : "=r"(r) : "f"(f));
    return r;
}

// m16n8k8 tf32 mma. c += a * b.
__device__ __forceinline__ void mma8(float* c, uint32_t a0, uint32_t a1,
                                     uint32_t a2, uint32_t a3,
                                     uint32_t b0, uint32_t b1) {
    asm volatile(
        "mma.sync.aligned.m16n8k8.row.col.f32.tf32.tf32.f32 "
        "{%0,%1,%2,%3},{%4,%5,%6,%7},{%8,%9},{%0,%1,%2,%3};"
        : "+f"(c[0]), "+f"(c[1]), "+f"(c[2]), "+f"(c[3])
        : "r"(a0), "r"(a1), "r"(a2), "r"(a3), "r"(b0), "r"(b1));
}

// Permute k within each 8-group so (k, k+4) become adjacent floats:
// pos = group*8 + (k%4)*2 + ((k/4)%2)
__device__ __forceinline__ int perm8(int k) {
    return (k & ~7) + ((k & 3) << 1) + ((k >> 2) & 1);
}

// ---------------------------------------------------------------------------
// QKV GEMM: C[m,n] = sum_k x[m,k]*w[n,k] + bias[n]. M=8192 N=3072 K=1024.
// CTA 128x128, k-chunk 32, double-buffered smem, tf32 mma.sync.
// Round 13: GP 36->40 (row stride = 8 mod 32 -> conflict-free fragment LDS.64).
// ---------------------------------------------------------------------------
#define GP 40                       // smem row pitch (floats), 8 mod 32
#define GEMM_SMEM (4 * 128 * GP * 4)   // 2 bufs x (A+B) = 81920 B

__global__ __launch_bounds__(256) void qkv_gemm_mma(const float* __restrict__ x,
                                                    const float* __restrict__ w,
                                                    const float* __restrict__ bias) {
    extern __shared__ float sm[];
    float* As = sm;                  // [2][128*GP]
    float* Bs = sm + 2 * 128 * GP;   // [2][128*GP]

    const int tid = threadIdx.x;
    const int wid = tid >> 5, lane = tid & 31;
    const int g = lane >> 2, tig = lane & 3;
    const int wm = (wid >> 1) * 32, wn = (wid & 1) * 64;
    const int n0 = blockIdx.x * 128;
    const int m0 = blockIdx.y * 128;
    const int c4 = tid & 7;          // float4 col index within 32-float chunk row

    float4 ar[4], br[4];
    float acc[2][8][4];
#pragma unroll
    for (int mi = 0; mi < 2; mi++)
#pragma unroll
        for (int ni = 0; ni < 8; ni++)
#pragma unroll
            for (int e = 0; e < 4; e++) acc[mi][ni][e] = 0.f;

#define LOADG(c) {                                                              \
    const float* Ap = x + (size_t)m0 * DIM + (c) * 32;                          \
    const float* Bp = w + (size_t)n0 * DIM + (c) * 32;                          \
    _Pragma("unroll")                                                           \
    for (int it = 0; it < 4; it++) {                                            \
        int r = (it * 256 + tid) >> 3;                                          \
        ar[it] = *(const float4*)(Ap + (size_t)r * DIM + c4 * 4);               \
        br[it] = *(const float4*)(Bp + (size_t)r * DIM + c4 * 4);               \
    } }

#define STORES(buf) {                                                           \
    float* ab = As + (buf) * 128 * GP;                                          \
    float* bb = Bs + (buf) * 128 * GP;                                          \
    _Pragma("unroll")                                                           \
    for (int it = 0; it < 4; it++) {                                            \
        int r = (it * 256 + tid) >> 3;                                          \
        float av[4] = {ar[it].x, ar[it].y, ar[it].z, ar[it].w};                 \
        float bv[4] = {br[it].x, br[it].y, br[it].z, br[it].w};                 \
        _Pragma("unroll")                                                       \
        for (int e = 0; e < 4; e++) {                                           \
            int p = perm8(c4 * 4 + e);                                          \
            ab[r * GP + p] = __uint_as_float(f2tf32(av[e]));                    \
            bb[r * GP + p] = __uint_as_float(f2tf32(bv[e]));                    \
        }                                                                       \
    } }

    LOADG(0);
    STORES(0);
    __syncthreads();

    int cur = 0;
    for (int c = 0; c < DIM / 32; c++) {
        if (c < DIM / 32 - 1) LOADG(c + 1);
        const float* ab = As + cur * 128 * GP;
        const float* bb = Bs + cur * 128 * GP;
#pragma unroll
        for (int s = 0; s < 4; s++) {
            float2 alo[2], ahi[2];
#pragma unroll
            for (int mi = 0; mi < 2; mi++) {
                int r0 = wm + mi * 16 + g;
                alo[mi] = *(const float2*)&ab[r0 * GP + s * 8 + tig * 2];
                ahi[mi] = *(const float2*)&ab[(r0 + 8) * GP + s * 8 + tig * 2];
            }
#pragma unroll
            for (int ni = 0; ni < 8; ni++) {
                float2 bf = *(const float2*)&bb[(wn + ni * 8 + g) * GP + s * 8 + tig * 2];
#pragma unroll
                for (int mi = 0; mi < 2; mi++) {
                    mma8(acc[mi][ni],
                         __float_as_uint(alo[mi].x), __float_as_uint(ahi[mi].x),
                         __float_as_uint(alo[mi].y), __float_as_uint(ahi[mi].y),
                         __float_as_uint(bf.x), __float_as_uint(bf.y));
                }
            }
        }
        if (c < DIM / 32 - 1) STORES(cur ^ 1);
        __syncthreads();
        cur ^= 1;
    }

    // Epilogue: bias + scale, round to tf32, scatter to g_q/g_k/g_v.
    const int nb = n0 + wn;                 // 64-aligned -> single (seg, head)
    const int seg = nb >> 10;
    const int h = (nb & 1023) >> 6;
    float* dst = (seg == 0) ? g_q : (seg == 1) ? g_k : g_v;
    const float sc = (seg == 0) ? SCALE : 1.0f;

#pragma unroll
    for (int mi = 0; mi < 2; mi++) {
        int r0 = m0 + wm + mi * 16 + g;     // and r0+8
        int bb0 = r0 >> 11;                  // /2048
        int nrow = r0 & 2047;
        float* d0 = dst + ((size_t)(bb0 * NH + h) * Nseq + nrow) * HD;
        float* d1 = d0 + 8 * HD;             // row r0+8 (same batch)
#pragma unroll
        for (int ni = 0; ni < 8; ni++) {
            int dcol = ni * 8 + 2 * tig;
            float b0 = bias[nb + dcol], b1 = bias[nb + dcol + 1];
            float2 v0, v1;
            v0.x = __uint_as_float(f2tf32((acc[mi][ni][0] + b0) * sc));
            v0.y = __uint_as_float(f2tf32((acc[mi][ni][1] + b1) * sc));
            v1.x = __uint_as_float(f2tf32((acc[mi][ni][2] + b0) * sc));
            v1.y = __uint_as_float(f2tf32((acc[mi][ni][3] + b1) * sc));
            *(float2*)&d0[dcol] = v0;
            *(float2*)&d1[dcol] = v1;
        }
    }
}

// ---------------------------------------------------------------------------
// Flash attention, tf32 mma. CTA = 128 queries x 64-key tiles, 8 warps.
// Round 13: AP 68->72 (conflict-free fragment LDS.64); K fill as paired STS.64.
// ---------------------------------------------------------------------------
#define AP 72                        // smem row pitch (floats), 8 mod 32
#define KS_OFF 0
#define VS_OFF (64 * AP)
#define PS_OFF (128 * AP)
#define ATTN_SMEM ((PS_OFF + 128 * AP) * 4)   // 73728 B

__global__ __launch_bounds__(256, 2) void attn_mma(float* __restrict__ out) {
    extern __shared__ float sm[];
    float* Ks = sm + KS_OFF;   // [64][AP],  perm over d
    float* Vs = sm + VS_OFF;   // [64(d)][AP], transposed, perm over key
    float* Ps = sm + PS_OFF;   // [128][AP]

    const int bh = blockIdx.x;
    const int q0 = blockIdx.y * 128;
    const float* Qg = g_q + (size_t)bh * Nseq * HD;
    const float* Kg = g_k + (size_t)bh * Nseq * HD;
    const float* Vg = g_v + (size_t)bh * Nseq * HD;

    const int tid = threadIdx.x;
    const int wid = tid >> 5, lane = tid & 31;
    const int g = lane >> 2, tig = lane & 3;
    const int r0 = wid * 16 + g;           // warp-owned rows r0, r0+8

    // Q a-fragments in registers (values already tf32-rounded by GEMM).
    uint32_t qf[8][4];
    {
        const float* q0p = Qg + (size_t)(q0 + r0) * HD;
        const float* q1p = q0p + 8 * HD;
#pragma unroll
        for (int s = 0; s < 8; s++) {
            qf[s][0] = __float_as_uint(q0p[s * 8 + tig]);
            qf[s][1] = __float_as_uint(q1p[s * 8 + tig]);
            qf[s][2] = __float_as_uint(q0p[s * 8 + tig + 4]);
            qf[s][3] = __float_as_uint(q1p[s * 8 + tig + 4]);
        }
    }

    // K-load mapping: 4 threads per row, 16 floats each.
    const int krow = tid >> 2;
    const int kdc = (tid & 3) << 4;
    // V-load mapping: lane = row (conflict-free transposed stores).
    const int vrow = tid & 63;
    const int vdc = (tid >> 6) << 4;

    float o[8][4];
#pragma unroll
    for (int ni = 0; ni < 8; ni++)
#pragma unroll
        for (int e = 0; e < 4; e++) o[ni][e] = 0.f;
    float m0r = -INFINITY, m1r = -INFINITY, l0 = 0.f, l1 = 0.f;

    for (int t = 0; t < Nseq; t += 64) {
        // K tile: load 16 floats, store as paired (k_i, k_{i+4}) STS.64 —
        // matches perm8 layout, fewer/faster shared stores.
        {
            float kreg[16];
#pragma unroll
            for (int j = 0; j < 4; j++) {
                float4 k4 = *(const float4*)(Kg + (size_t)(t + krow) * HD + kdc + j * 4);
                kreg[j * 4 + 0] = k4.x; kreg[j * 4 + 1] = k4.y;
                kreg[j * 4 + 2] = k4.z; kreg[j * 4 + 3] = k4.w;
            }
#pragma unroll
            for (int G = 0; G < 2; G++)
#pragma unroll
                for (int i = 0; i < 4; i++) {
                    float2 p = make_float2(kreg[G * 8 + i], kreg[G * 8 + i + 4]);
                    *(float2*)&Ks[krow * AP + kdc + G * 8 + 2 * i] = p;
                }
        }
        // V tile transposed: Vs[d][perm8(r)]
#pragma unroll
        for (int j = 0; j < 4; j++) {
            float4 v4 = *(const float4*)(Vg + (size_t)(t + vrow) * HD + vdc + j * 4);
            float vv[4] = {v4.x, v4.y, v4.z, v4.w};
#pragma unroll
            for (int e = 0; e < 4; e++)
                Vs[(vdc + j * 4 + e) * AP + perm8(vrow)] = vv[e];
        }
        __syncthreads();

        // S = Q K^T (Q from registers)
        float sfr[8][4];
#pragma unroll
        for (int ni = 0; ni < 8; ni++)
#pragma unroll
            for (int e = 0; e < 4; e++) sfr[ni][e] = 0.f;
#pragma unroll
        for (int s = 0; s < 8; s++) {
#pragma unroll
            for (int ni = 0; ni < 8; ni++) {
                float2 kb = *(const float2*)&Ks[(ni * 8 + g) * AP + s * 8 + tig * 2];
                mma8(sfr[ni], qf[s][0], qf[s][1], qf[s][2], qf[s][3],
                     __float_as_uint(kb.x), __float_as_uint(kb.y));
            }
        }

        // Online softmax (rows r0 and r0+8; reduce across the 4 tig lanes).
        float mx0 = -INFINITY, mx1 = -INFINITY;
#pragma unroll
        for (int ni = 0; ni < 8; ni++) {
            mx0 = fmaxf(mx0, fmaxf(sfr[ni][0], sfr[ni][1]));
            mx1 = fmaxf(mx1, fmaxf(sfr[ni][2], sfr[ni][3]));
        }
        mx0 = fmaxf(mx0, __shfl_xor_sync(0xffffffffu, mx0, 1));
        mx0 = fmaxf(mx0, __shfl_xor_sync(0xffffffffu, mx0, 2));
        mx1 = fmaxf(mx1, __shfl_xor_sync(0xffffffffu, mx1, 1));
        mx1 = fmaxf(mx1, __shfl_xor_sync(0xffffffffu, mx1, 2));
        float nm0 = fmaxf(m0r, mx0), nm1 = fmaxf(m1r, mx1);
        float al0 = __expf(m0r - nm0), al1 = __expf(m1r - nm1);
        m0r = nm0; m1r = nm1;
        float rs0 = 0.f, rs1 = 0.f;
#pragma unroll
        for (int ni = 0; ni < 8; ni++) {
            sfr[ni][0] = __expf(sfr[ni][0] - nm0);
            sfr[ni][1] = __expf(sfr[ni][1] - nm0);
            sfr[ni][2] = __expf(sfr[ni][2] - nm1);
            sfr[ni][3] = __expf(sfr[ni][3] - nm1);
            rs0 += sfr[ni][0] + sfr[ni][1];
            rs1 += sfr[ni][2] + sfr[ni][3];
        }
        rs0 += __shfl_xor_sync(0xffffffffu, rs0, 1);
        rs0 += __shfl_xor_sync(0xffffffffu, rs0, 2);
        rs1 += __shfl_xor_sync(0xffffffffu, rs1, 1);
        rs1 += __shfl_xor_sync(0xffffffffu, rs1, 2);
        l0 = l0 * al0 + rs0;
        l1 = l1 * al1 + rs1;
#pragma unroll
        for (int ni = 0; ni < 8; ni++) {
            o[ni][0] *= al0; o[ni][1] *= al0;
            o[ni][2] *= al1; o[ni][3] *= al1;
        }

        // Store P (tf32-rounded) — warp-local region.
#pragma unroll
        for (int ni = 0; ni < 8; ni++) {
            float2 p0, p1;
            p0.x = __uint_as_float(f2tf32(sfr[ni][0]));
            p0.y = __uint_as_float(f2tf32(sfr[ni][1]));
            p1.x = __uint_as_float(f2tf32(sfr[ni][2]));
            p1.y = __uint_as_float(f2tf32(sfr[ni][3]));
            *(float2*)&Ps[r0 * AP + ni * 8 + 2 * tig] = p0;
            *(float2*)&Ps[(r0 + 8) * AP + ni * 8 + 2 * tig] = p1;
        }
        __syncwarp();

        // O += P V
        const uint32_t* Pu = (const uint32_t*)Ps;
#pragma unroll
        for (int s = 0; s < 8; s++) {
            uint32_t a0 = Pu[r0 * AP + s * 8 + tig];
            uint32_t a1 = Pu[(r0 + 8) * AP + s * 8 + tig];
            uint32_t a2 = Pu[r0 * AP + s * 8 + tig + 4];
            uint32_t a3 = Pu[(r0 + 8) * AP + s * 8 + tig + 4];
#pragma unroll
            for (int ni = 0; ni < 8; ni++) {
                float2 vb = *(const float2*)&Vs[(ni * 8 + g) * AP + s * 8 + tig * 2];
                mma8(o[ni], a0, a1, a2, a3,
                     __float_as_uint(vb.x), __float_as_uint(vb.y));
            }
        }
        __syncthreads();
    }

    // Final write: out[b, q, h*64 + d]
    const int bb = bh >> 4;
    const int h = bh & 15;
    float inv0 = 1.0f / l0, inv1 = 1.0f / l1;
    float* p0 = out + ((size_t)(bb * Nseq + q0 + r0)) * DIM + h * HD;
    float* p1 = out + ((size_t)(bb * Nseq + q0 + r0 + 8)) * DIM + h * HD;
#pragma unroll
    for (int ni = 0; ni < 8; ni++) {
        int d = ni * 8 + 2 * tig;
        float2 v0 = make_float2(o[ni][0] * inv0, o[ni][1] * inv0);
        float2 v1 = make_float2(o[ni][2] * inv1, o[ni][3] * inv1);
        *(float2*)&p0[d] = v0;
        *(float2*)&p1[d] = v1;
    }
}

extern "C" void kernel_launch(void* const* d_in, const int* in_sizes, int n_in,
                              void* d_out, int out_size) {
    const float* x = (const float*)d_in[0];
    const float* w = (const float*)d_in[1];
    const float* bias = (const float*)d_in[2];
    float* out = (float*)d_out;

    cudaFuncSetAttribute(qkv_gemm_mma,
                         cudaFuncAttributeMaxDynamicSharedMemorySize, GEMM_SMEM);
    cudaFuncSetAttribute(attn_mma,
                         cudaFuncAttributeMaxDynamicSharedMemorySize, ATTN_SMEM);
    cudaFuncSetAttribute(attn_mma,
                         cudaFuncAttributePreferredSharedMemoryCarveout, 100);

    dim3 ggrid(3 * DIM / 128, Bdim * Nseq / 128);  // (24, 64)
    qkv_gemm_mma<<<ggrid, 256, GEMM_SMEM>>>(x, w, bias);

    dim3 agrid(Bdim * NH, Nseq / 128);             // (64, 16)
    attn_mma<<<agrid, 256, ATTN_SMEM>>>(out);
}